// round 8
// baseline (speedup 1.0000x reference)
#include <cuda_runtime.h>
#include <cstdint>

#define BB 4
#define TT 2048
#define CC 576
#define HH 12
#define DD 48
#define MM (BB*TT)       /* 8192 */
#define NQKV (3*CC)      /* 1728 */

// Scratch (device globals: allocation-free). q/k/v stored pre-rounded to tf32
// (q additionally pre-scaled by 1/sqrt(48)). y stored pre-rounded by attention.
__device__ float g_q[BB*HH*TT*DD];
__device__ float g_k[BB*HH*TT*DD];
__device__ float g_v[BB*HH*TT*DD];
__device__ float g_y[BB*TT*CC];
__device__ float g_xr[MM*CC];       // tf32-rounded x
__device__ float g_wqr[NQKV*CC];    // tf32-rounded w_qkv
__device__ float g_wpr[CC*CC];      // tf32-rounded w_proj

// ---------------------------------------------------------------------------
// helpers
// ---------------------------------------------------------------------------
__device__ __forceinline__ unsigned f2tf(float x) {
    unsigned r;
    asm("cvt.rna.tf32.f32 %0, %1;" : "=r"(r) : "f"(x));
    return r;
}

__device__ __forceinline__ void mma_tf32(float c[4],
                                         unsigned a0, unsigned a1, unsigned a2, unsigned a3,
                                         unsigned b0, unsigned b1) {
    asm volatile(
        "mma.sync.aligned.m16n8k8.row.col.f32.tf32.tf32.f32 "
        "{%0,%1,%2,%3}, {%4,%5,%6,%7}, {%8,%9}, {%0,%1,%2,%3};"
        : "+f"(c[0]), "+f"(c[1]), "+f"(c[2]), "+f"(c[3])
        : "r"(a0), "r"(a1), "r"(a2), "r"(a3), "r"(b0), "r"(b1));
}

// FMA-pipe exp (no MUFU): exp(x) for x <= 0, rel err ~3e-6.
__device__ __forceinline__ float fexp(float x) {
    x = fmaxf(x, -80.f);
    float u = x * 1.4426950408889634f;
    float t = u + 12582912.f;
    int   i = __float_as_int(t) - 0x4B400000;
    float f = u - (t - 12582912.f);
    float p = fmaf(f, 0.0013333558f, 0.0096181291f);
    p = fmaf(f, p, 0.055504109f);
    p = fmaf(f, p, 0.24022651f);
    p = fmaf(f, p, 0.69314718f);
    p = fmaf(f, p, 1.0f);
    return p * __int_as_float((i + 127) << 23);
}

__device__ __forceinline__ void cp16(uint32_t saddr, const void* gp) {
    asm volatile("cp.async.cg.shared.global [%0], [%1], 16;"
                 :: "r"(saddr), "l"(__cvta_generic_to_global(gp)));
}
__device__ __forceinline__ void cp_commit() {
    asm volatile("cp.async.commit_group;");
}

// ---------------------------------------------------------------------------
// prep: elementwise tf32 rounding (rna) of GEMM inputs
// ---------------------------------------------------------------------------
__global__ void round_tf32(const float* __restrict__ src, float* __restrict__ dst, int n4)
{
    int i = blockIdx.x * blockDim.x + threadIdx.x;
    if (i < n4) {
        float4 v = ((const float4*)src)[i];
        float4 s;
        s.x = __uint_as_float(f2tf(v.x));
        s.y = __uint_as_float(f2tf(v.y));
        s.z = __uint_as_float(f2tf(v.z));
        s.w = __uint_as_float(f2tf(v.w));
        ((float4*)dst)[i] = s;
    }
}

// ---------------------------------------------------------------------------
// TF32 tensor-core GEMM: out[m][n] = sum_k A[m][k]*W[n][k], K = 576 fixed.
// A, W PRE-ROUNDED to tf32. CTA 256x64, 256 threads = 8 warps; warp tile
// 32x64 (acc = 64 regs/thread). BK=32, cp.async double-buffered.
// scatter!=0: qkv epilogue -> g_q (pre-scaled) / g_k / g_v, tf32-rounded.
// ---------------------------------------------------------------------------
#define GS 36                     /* smem row stride: 32 + 4 pad, 16B aligned */
#define GA_FLOATS (256*GS)
#define GB_FLOATS (64*GS)
#define GBUF (GA_FLOATS + GB_FLOATS)
#define GSM_BYTES (2*GBUF*4)

extern __shared__ float sm_dyn[];

__global__ __launch_bounds__(256) void gemm_tc(
    const float* __restrict__ A, const float* __restrict__ W,
    float* __restrict__ out, int Ndim, int scatter)
{
    const int tid  = threadIdx.x;
    const int wid  = tid >> 5, lane = tid & 31;
    const int g    = lane >> 2, c = lane & 3;
    const int m0   = blockIdx.y * 256;
    const int n0   = blockIdx.x * 64;
    const uint32_t smbase = (uint32_t)__cvta_generic_to_shared(sm_dyn);

    float acc[2][8][4];
#pragma unroll
    for (int i = 0; i < 2; i++)
#pragma unroll
        for (int j = 0; j < 8; j++)
#pragma unroll
            for (int e = 0; e < 4; e++) acc[i][j][e] = 0.f;

    auto issue = [&](int it) {
        const int k0 = it * 32;
        const uint32_t base = smbase + (uint32_t)(it & 1) * (GBUF * 4);
#pragma unroll
        for (int i = 0; i < 8; i++) {
            const int ch = tid + i * 256;
            const int row = ch >> 3, cq = ch & 7;
            cp16(base + (uint32_t)(row * GS + cq * 4) * 4,
                 A + (size_t)(m0 + row) * 576 + k0 + cq * 4);
        }
        const uint32_t bb = base + GA_FLOATS * 4;
#pragma unroll
        for (int i = 0; i < 2; i++) {
            const int ch = tid + i * 256;
            const int row = ch >> 3, cq = ch & 7;
            cp16(bb + (uint32_t)(row * GS + cq * 4) * 4,
                 W + (size_t)(n0 + row) * 576 + k0 + cq * 4);
        }
        cp_commit();
    };

    issue(0);
    for (int it = 0; it < 18; it++) {
        if (it + 1 < 18) {
            issue(it + 1);
            asm volatile("cp.async.wait_group 1;");
        } else {
            asm volatile("cp.async.wait_group 0;");
        }
        __syncthreads();
        const float* As = sm_dyn + (it & 1) * GBUF;
        const float* Bs = As + GA_FLOATS;

#pragma unroll
        for (int kk = 0; kk < 4; kk++) {
            const int kb = kk * 8;
            unsigned a[2][4];
#pragma unroll
            for (int i = 0; i < 2; i++) {
                const int mr = wid * 32 + i * 16;
                a[i][0] = __float_as_uint(As[(mr + g) * GS + kb + c]);
                a[i][1] = __float_as_uint(As[(mr + g + 8) * GS + kb + c]);
                a[i][2] = __float_as_uint(As[(mr + g) * GS + kb + c + 4]);
                a[i][3] = __float_as_uint(As[(mr + g + 8) * GS + kb + c + 4]);
            }
#pragma unroll
            for (int j = 0; j < 8; j++) {
                unsigned b0 = __float_as_uint(Bs[(j * 8 + g) * GS + kb + c]);
                unsigned b1 = __float_as_uint(Bs[(j * 8 + g) * GS + kb + c + 4]);
#pragma unroll
                for (int i = 0; i < 2; i++)
                    mma_tf32(acc[i][j], a[i][0], a[i][1], a[i][2], a[i][3], b0, b1);
            }
        }
        __syncthreads();
    }

    const float qscale = 0.14433756729740643f;  // 1/sqrt(48)
#pragma unroll
    for (int i = 0; i < 2; i++) {
#pragma unroll
        for (int j = 0; j < 8; j++) {
            const int col = n0 + j * 8 + 2 * c;
#pragma unroll
            for (int half = 0; half < 2; half++) {
                const int m = m0 + wid * 32 + i * 16 + g + half * 8;
                float v0 = acc[i][j][half * 2 + 0];
                float v1 = acc[i][j][half * 2 + 1];
                if (scatter) {
                    const int b = m >> 11, t = m & 2047;
                    const int which = col / CC;
                    const int cc = col - which * CC;
                    const int h = cc / DD, d = cc - h * DD;
                    float* dst = (which == 0) ? g_q : (which == 1) ? g_k : g_v;
                    if (which == 0) { v0 *= qscale; v1 *= qscale; }
                    float2 st;
                    st.x = __uint_as_float(f2tf(v0));
                    st.y = __uint_as_float(f2tf(v1));
                    *(float2*)&dst[(((size_t)b * HH + h) * TT + t) * DD + d] = st;
                } else {
                    float2 st; st.x = v0; st.y = v1;
                    *(float2*)&out[(size_t)m * Ndim + col] = st;
                }
            }
        }
    }
}

// ---------------------------------------------------------------------------
// Flash attention, tf32 tensor cores. BR=128, BC=64, 256 threads = 8 warps.
// Warp w owns rows w*16..w*16+15 (ONE m16 fragment -> low regs, high occ).
// K/V double-buffered via cp.async. P re-fragmentation via warp shuffles.
// Heavy CTAs (large rb) launch first via reversed blockIdx.x.
// ---------------------------------------------------------------------------
#define AK 52
#define AV 56
#define OFF_K0 0
#define OFF_K1 (64*AK)
#define OFF_V0 (2*64*AK)
#define OFF_V1 (2*64*AK + 64*AV)
#define ASM_BYTES ((2*64*AK + 2*64*AV) * 4)

__global__ __launch_bounds__(256) void attn_tc(float* __restrict__ ypre)
{
    const int rb = (gridDim.x - 1) - blockIdx.x;   // heavy blocks first
    const int h = blockIdx.y, b = blockIdx.z;
    const int tid = threadIdx.x, wid = tid >> 5, lane = tid & 31;
    const int g = lane >> 2, c = lane & 3;
    const int t0 = rb * 128;
    const int nblk = 2 * rb + 2;
    const size_t bh = ((size_t)b * HH + h) * TT;

    // Q a-fragments (rows t0 + wid*16 .. +15), pre-scaled & tf32-rounded
    unsigned qa[6][4];
    {
        const float* Qb = g_q + (bh + t0 + wid * 16) * DD;
#pragma unroll
        for (int k = 0; k < 6; k++) {
            qa[k][0] = __float_as_uint(Qb[(g) * DD + k * 8 + c]);
            qa[k][1] = __float_as_uint(Qb[(g + 8) * DD + k * 8 + c]);
            qa[k][2] = __float_as_uint(Qb[(g) * DD + k * 8 + c + 4]);
            qa[k][3] = __float_as_uint(Qb[(g + 8) * DD + k * 8 + c + 4]);
        }
    }

    float o[6][4];
#pragma unroll
    for (int nf = 0; nf < 6; nf++)
#pragma unroll
        for (int e = 0; e < 4; e++) o[nf][e] = 0.f;
    float mA = -1e30f, mB = -1e30f, lA = 0.f, lB = 0.f;

    // K/V loaders: 256 threads, 64 rows x 12 float4 -> 3 chunks per thread
    const int ldrow = tid >> 2, ldd = (tid & 3) * 12;
    const uint32_t smbase = (uint32_t)__cvta_generic_to_shared(sm_dyn);
    const int srcA = (lane & ~3) | (c >> 1);       // P-shuffle source lanes
    const int srcB = srcA + 2;
    const bool odd = (c & 1);

    {
        const float* Kp = g_k + (bh + ldrow) * DD + ldd;
        const float* Vp = g_v + (bh + ldrow) * DD + ldd;
        const uint32_t kd = smbase + (OFF_K0 + ldrow * AK + ldd) * 4;
        const uint32_t vd = smbase + (OFF_V0 + ldrow * AV + ldd) * 4;
#pragma unroll
        for (int i = 0; i < 3; i++) {
            cp16(kd + i * 16, Kp + i * 4);
            cp16(vd + i * 16, Vp + i * 4);
        }
        cp_commit();
    }

    for (int jb = 0; jb < nblk; jb++) {
        const int cur = jb & 1;
        if (jb + 1 < nblk) {
            const float* Kp = g_k + (bh + (size_t)(jb + 1) * 64 + ldrow) * DD + ldd;
            const float* Vp = g_v + (bh + (size_t)(jb + 1) * 64 + ldrow) * DD + ldd;
            const uint32_t kd = smbase + (((jb + 1) & 1 ? OFF_K1 : OFF_K0) + ldrow * AK + ldd) * 4;
            const uint32_t vd = smbase + (((jb + 1) & 1 ? OFF_V1 : OFF_V0) + ldrow * AV + ldd) * 4;
#pragma unroll
            for (int i = 0; i < 3; i++) {
                cp16(kd + i * 16, Kp + i * 4);
                cp16(vd + i * 16, Vp + i * 4);
            }
            cp_commit();
            asm volatile("cp.async.wait_group 1;");
        } else {
            asm volatile("cp.async.wait_group 0;");
        }
        __syncthreads();

        const float* Ks = sm_dyn + (cur ? OFF_K1 : OFF_K0);
        const float* Vs = sm_dyn + (cur ? OFF_V1 : OFF_V0);

        // S = Q K^T
        float s[8][4];
#pragma unroll
        for (int f = 0; f < 8; f++)
#pragma unroll
            for (int e = 0; e < 4; e++) s[f][e] = 0.f;
#pragma unroll
        for (int f = 0; f < 8; f++) {
#pragma unroll
            for (int k = 0; k < 6; k++) {
                unsigned b0 = __float_as_uint(Ks[(f * 8 + g) * AK + k * 8 + c]);
                unsigned b1 = __float_as_uint(Ks[(f * 8 + g) * AK + k * 8 + c + 4]);
                mma_tf32(s[f], qa[k][0], qa[k][1], qa[k][2], qa[k][3], b0, b1);
            }
        }

        if (jb >= 2 * rb) {
            const int off = (jb - 2 * rb) * 64;
            const int ra  = wid * 16 + g - off;
            const int ra8 = ra + 8;
#pragma unroll
            for (int f = 0; f < 8; f++) {
                const int col = f * 8 + 2 * c;
                if (col > ra)       s[f][0] = -1e30f;
                if (col + 1 > ra)   s[f][1] = -1e30f;
                if (col > ra8)      s[f][2] = -1e30f;
                if (col + 1 > ra8)  s[f][3] = -1e30f;
            }
        }

        // online softmax (FMA-pipe exp)
        {
            float mja = -1e30f, mjb = -1e30f;
#pragma unroll
            for (int f = 0; f < 8; f++) {
                mja = fmaxf(mja, fmaxf(s[f][0], s[f][1]));
                mjb = fmaxf(mjb, fmaxf(s[f][2], s[f][3]));
            }
            mja = fmaxf(mja, __shfl_xor_sync(0xffffffffu, mja, 1));
            mja = fmaxf(mja, __shfl_xor_sync(0xffffffffu, mja, 2));
            mjb = fmaxf(mjb, __shfl_xor_sync(0xffffffffu, mjb, 1));
            mjb = fmaxf(mjb, __shfl_xor_sync(0xffffffffu, mjb, 2));
            const float mna = fmaxf(mA, mja), mnb = fmaxf(mB, mjb);
            const float ca = fexp(mA - mna), cb = fexp(mB - mnb);
            float psa = 0.f, psb = 0.f;
#pragma unroll
            for (int f = 0; f < 8; f++) {
                s[f][0] = fexp(s[f][0] - mna); psa += s[f][0];
                s[f][1] = fexp(s[f][1] - mna); psa += s[f][1];
                s[f][2] = fexp(s[f][2] - mnb); psb += s[f][2];
                s[f][3] = fexp(s[f][3] - mnb); psb += s[f][3];
            }
            mA = mna; mB = mnb;
            lA = lA * ca + psa;
            lB = lB * cb + psb;
#pragma unroll
            for (int nf = 0; nf < 6; nf++) {
                o[nf][0] *= ca; o[nf][1] *= ca;
                o[nf][2] *= cb; o[nf][3] *= cb;
            }
        }

        // O += P V  — P a-frags built from S c-frags via 4-lane shuffles.
#pragma unroll
        for (int k = 0; k < 8; k++) {
            unsigned pa[4];
            {
                float u0 = __shfl_sync(0xffffffffu, s[k][0], srcA);
                float u1 = __shfl_sync(0xffffffffu, s[k][1], srcA);
                float u2 = __shfl_sync(0xffffffffu, s[k][2], srcA);
                float u3 = __shfl_sync(0xffffffffu, s[k][3], srcA);
                float w0 = __shfl_sync(0xffffffffu, s[k][0], srcB);
                float w1 = __shfl_sync(0xffffffffu, s[k][1], srcB);
                float w2 = __shfl_sync(0xffffffffu, s[k][2], srcB);
                float w3 = __shfl_sync(0xffffffffu, s[k][3], srcB);
                pa[0] = __float_as_uint(odd ? u1 : u0);
                pa[1] = __float_as_uint(odd ? u3 : u2);
                pa[2] = __float_as_uint(odd ? w1 : w0);
                pa[3] = __float_as_uint(odd ? w3 : w2);
            }
#pragma unroll
            for (int nf = 0; nf < 6; nf++) {
                unsigned b0 = __float_as_uint(Vs[(k * 8 + c) * AV + nf * 8 + g]);
                unsigned b1 = __float_as_uint(Vs[(k * 8 + c + 4) * AV + nf * 8 + g]);
                mma_tf32(o[nf], pa[0], pa[1], pa[2], pa[3], b0, b1);
            }
        }
        __syncthreads();
    }

    // finalize (y stored tf32-rounded for the proj GEMM)
    {
        float la = lA, lb = lB;
        la += __shfl_xor_sync(0xffffffffu, la, 1);
        la += __shfl_xor_sync(0xffffffffu, la, 2);
        lb += __shfl_xor_sync(0xffffffffu, lb, 1);
        lb += __shfl_xor_sync(0xffffffffu, lb, 2);
        const float ia = 1.f / la, ib = 1.f / lb;
        const int ra = t0 + wid * 16 + g;
        float* ya = ypre + ((size_t)b * TT + ra) * CC + h * DD;
        float* yb = ypre + ((size_t)b * TT + ra + 8) * CC + h * DD;
#pragma unroll
        for (int nf = 0; nf < 6; nf++) {
            const int d = nf * 8 + 2 * c;
            float2 sa, sb;
            sa.x = __uint_as_float(f2tf(o[nf][0] * ia));
            sa.y = __uint_as_float(f2tf(o[nf][1] * ia));
            sb.x = __uint_as_float(f2tf(o[nf][2] * ib));
            sb.y = __uint_as_float(f2tf(o[nf][3] * ib));
            *(float2*)&ya[d] = sa;
            *(float2*)&yb[d] = sb;
        }
    }
}

extern "C" void kernel_launch(void* const* d_in, const int* in_sizes, int n_in,
                              void* d_out, int out_size)
{
    (void)in_sizes; (void)n_in; (void)out_size;
    const float* x      = (const float*)d_in[0];
    const float* w_qkv  = (const float*)d_in[1];
    const float* w_proj = (const float*)d_in[2];
    float* out = (float*)d_out;

    float *yptr = nullptr, *xr = nullptr, *wqr = nullptr, *wpr = nullptr;
    cudaGetSymbolAddress((void**)&yptr, g_y);
    cudaGetSymbolAddress((void**)&xr,  g_xr);
    cudaGetSymbolAddress((void**)&wqr, g_wqr);
    cudaGetSymbolAddress((void**)&wpr, g_wpr);

    cudaFuncSetAttribute(gemm_tc, cudaFuncAttributeMaxDynamicSharedMemorySize, GSM_BYTES);
    cudaFuncSetAttribute(attn_tc, cudaFuncAttributeMaxDynamicSharedMemorySize, ASM_BYTES);

    // 0) pre-round GEMM inputs to tf32 (rna)
    round_tf32<<<(MM*CC/4 + 255)/256, 256>>>(x, xr, MM*CC/4);
    round_tf32<<<(NQKV*CC/4 + 255)/256, 256>>>(w_qkv, wqr, NQKV*CC/4);
    round_tf32<<<(CC*CC/4 + 255)/256, 256>>>(w_proj, wpr, CC*CC/4);

    // 1) qkv GEMM -> scatter q/k/v [B,H,T,D]
    {
        dim3 grid(NQKV / 64, MM / 256);
        gemm_tc<<<grid, 256, GSM_BYTES>>>(xr, wqr, nullptr, NQKV, 1);
    }
    // 2) causal flash attention -> g_y [B,T,C] (tf32-rounded)
    {
        dim3 grid(TT / 128, HH, BB);
        attn_tc<<<grid, 256, ASM_BYTES>>>(yptr);
    }
    // 3) output projection
    {
        dim3 grid(CC / 64, MM / 256);
        gemm_tc<<<grid, 256, GSM_BYTES>>>(yptr, wpr, out, CC, 0);
    }
}